// round 1
// baseline (speedup 1.0000x reference)
#include <cuda_runtime.h>
#include <math.h>

#define NPTS 8192
#define MB   64
#define NBALL 128
#define DIM  64
#define NH   8
#define EHD  8
#define HID  256
#define EPSF 1.1920929e-07f

// ---------------- scratch (device globals; no allocation) ----------------
__device__ float g_xa[NPTS * DIM];     // rmsnorm(x)+rel  (attention input)
__device__ float g_keys[NBALL * DIM];  // per-ball mean of xa
__device__ int   g_idx[NPTS * NH * 2]; // top-2 ball indices per (n,h)
__device__ float g_h[NPTS * DIM];      // x + attn out (residual stream)
__device__ float g_hid[NPTS * HID];    // swiglu hidden
__device__ float g_w1t[DIM * HID];     // w1 transposed [d][k]
__device__ float g_w2t[DIM * HID];     // w2 transposed [d][k]
__device__ float g_w3t[HID * DIM];     // w3 transposed [k][d]

// ---------------- K0: weight transposes ----------------
__global__ void k_transpose(const float* __restrict__ w1,
                            const float* __restrict__ w2,
                            const float* __restrict__ w3) {
    int i = blockIdx.x * 256 + threadIdx.x;   // 0..16383
    if (i < DIM * HID) {
        // w1,w2: (256,64) row-major -> [d][k]
        int k = i >> 6, d = i & 63;
        g_w1t[d * HID + k] = w1[i];
        g_w2t[d * HID + k] = w2[i];
        // w3: (64,256) row-major -> [k][d]
        int d3 = i >> 8, k3 = i & 255;
        g_w3t[k3 * DIM + d3] = w3[i];
    }
}

// ---------------- K1: per-ball prep ----------------
// xa = rmsnorm(x)*w + (pos - ball_mean(pos)); keys = ball_mean(xa)
__global__ void k_ball(const float* __restrict__ x,
                       const float* __restrict__ pos,
                       const float* __restrict__ n1w) {
    __shared__ float xs[MB][DIM + 1];
    __shared__ float ps[MB][DIM + 1];
    __shared__ float pm[DIM];
    __shared__ float wsm[DIM];
    int b = blockIdx.x, tid = threadIdx.x;
    const float* xb = x + b * (MB * DIM);
    const float* pb = pos + b * (MB * DIM);
    for (int i = tid; i < MB * DIM; i += 256) {
        int r = i >> 6, d = i & 63;
        xs[r][d] = xb[i];
        ps[r][d] = pb[i];
    }
    if (tid < DIM) wsm[tid] = n1w[tid];
    __syncthreads();
    if (tid < DIM) {
        float s = 0.f;
        #pragma unroll
        for (int r = 0; r < MB; r++) s += ps[r][tid];
        pm[tid] = s * (1.f / MB);
    }
    __syncthreads();
    // 4 threads per row, 16 dims each
    int r = tid >> 2, part = tid & 3, d0 = part * 16;
    float ss = 0.f;
    #pragma unroll
    for (int j = 0; j < 16; j++) { float v = xs[r][d0 + j]; ss += v * v; }
    ss += __shfl_xor_sync(0xffffffffu, ss, 1);
    ss += __shfl_xor_sync(0xffffffffu, ss, 2);
    float rs = rsqrtf(ss * (1.f / DIM) + EPSF);
    float vals[16];
    #pragma unroll
    for (int j = 0; j < 16; j++) {
        int d = d0 + j;
        vals[j] = xs[r][d] * rs * wsm[d] + ps[r][d] - pm[d];
    }
    float* out = g_xa + (b * MB + r) * DIM + d0;
    #pragma unroll
    for (int j = 0; j < 16; j++) { xs[r][d0 + j] = vals[j]; out[j] = vals[j]; }
    __syncthreads();
    if (tid < DIM) {
        float s = 0.f;
        #pragma unroll
        for (int r2 = 0; r2 < MB; r2++) s += xs[r2][tid];
        g_keys[b * DIM + tid] = s * (1.f / MB);
    }
}

// ---------------- K2: routing (top-2 balls per (n,h)) ----------------
// softmax is monotonic and gates==1.0 forward -> only argtop-2 of q.keys needed
__global__ void k_route() {
    __shared__ float ks[NBALL * DIM];  // 32KB
    int tid = threadIdx.x;
    for (int i = tid; i < NBALL * DIM; i += 256) ks[i] = g_keys[i];
    __syncthreads();
    int g = blockIdx.x * 256 + tid;    // (n,h) flat, h fastest
    int n = g >> 3, h = g & 7;
    const float4* qp = (const float4*)(g_xa + n * DIM + h * EHD);
    float4 qa = qp[0], qb = qp[1];
    float v0 = -3.4e38f, v1 = -3.4e38f;
    int i0 = 0, i1 = 0;
    #pragma unroll 4
    for (int b = 0; b < NBALL; b++) {
        const float4* kp = (const float4*)(ks + b * DIM + h * EHD);
        float4 kA = kp[0], kB = kp[1];
        float s = qa.x * kA.x + qa.y * kA.y + qa.z * kA.z + qa.w * kA.w
                + qb.x * kB.x + qb.y * kB.y + qb.z * kB.z + qb.w * kB.w;
        if (s > v0) { v1 = v0; i1 = i0; v0 = s; i0 = b; }
        else if (s > v1) { v1 = s; i1 = b; }
    }
    g_idx[g * 2] = i0;
    g_idx[g * 2 + 1] = i1;
}

// ---------------- K3: attention (one warp per point) ----------------
__global__ void k_attn(const float* __restrict__ x) {
    __shared__ float qs[4][DIM];
    int w = threadIdx.x >> 5, lane = threadIdx.x & 31;
    int n = blockIdx.x * 4 + w;
    float2 t2 = ((const float2*)(g_xa + n * DIM))[lane];
    qs[w][lane * 2] = t2.x;
    qs[w][lane * 2 + 1] = t2.y;
    __syncwarp();
    const float scale = 0.35355339059327373f;  // 1/sqrt(8)
    for (int h = 0; h < NH; h++) {
        int base = (n * NH + h) * 2;
        int b0 = g_idx[base], b1 = g_idx[base + 1];
        float qh[EHD];
        #pragma unroll
        for (int e = 0; e < EHD; e++) qh[e] = qs[w][h * EHD + e];
        float4 kA[4], kB[4];
        float sc[4];
        #pragma unroll
        for (int ji = 0; ji < 4; ji++) {
            int j = lane + ji * 32;
            int row = (j < 64) ? (b0 * MB + j) : (b1 * MB + (j - 64));
            const float4* kp = (const float4*)(g_xa + row * DIM + h * EHD);
            kA[ji] = kp[0];
            kB[ji] = kp[1];
            sc[ji] = (qh[0] * kA[ji].x + qh[1] * kA[ji].y + qh[2] * kA[ji].z + qh[3] * kA[ji].w
                    + qh[4] * kB[ji].x + qh[5] * kB[ji].y + qh[6] * kB[ji].z + qh[7] * kB[ji].w) * scale;
        }
        float m = fmaxf(fmaxf(sc[0], sc[1]), fmaxf(sc[2], sc[3]));
        #pragma unroll
        for (int o = 16; o >= 1; o >>= 1) m = fmaxf(m, __shfl_xor_sync(0xffffffffu, m, o));
        float p[4], sum = 0.f;
        #pragma unroll
        for (int ji = 0; ji < 4; ji++) { p[ji] = __expf(sc[ji] - m); sum += p[ji]; }
        #pragma unroll
        for (int o = 16; o >= 1; o >>= 1) sum += __shfl_xor_sync(0xffffffffu, sum, o);
        float inv = 1.f / sum;
        float acc[EHD];
        #pragma unroll
        for (int e = 0; e < EHD; e++) acc[e] = 0.f;
        #pragma unroll
        for (int ji = 0; ji < 4; ji++) {
            acc[0] += p[ji] * kA[ji].x; acc[1] += p[ji] * kA[ji].y;
            acc[2] += p[ji] * kA[ji].z; acc[3] += p[ji] * kA[ji].w;
            acc[4] += p[ji] * kB[ji].x; acc[5] += p[ji] * kB[ji].y;
            acc[6] += p[ji] * kB[ji].z; acc[7] += p[ji] * kB[ji].w;
        }
        float outv = 0.f;
        #pragma unroll
        for (int e = 0; e < EHD; e++) {
            float v = acc[e];
            #pragma unroll
            for (int o = 16; o >= 1; o >>= 1) v += __shfl_xor_sync(0xffffffffu, v, o);
            if (lane == e) outv = v;
        }
        if (lane < EHD) {
            int o = n * DIM + h * EHD + lane;
            g_h[o] = x[o] + outv * inv;
        }
    }
}

// ---------------- K4: rmsnorm + dual GEMM + SwiGLU ----------------
// 32 rows x 256 cols per block; thread tile 8 rows x 4 cols
__global__ void k_mlp1(const float* __restrict__ n2w,
                       const float* __restrict__ b1p,
                       const float* __restrict__ b2p) {
    __shared__ float ts[32][DIM + 1];
    int tid = threadIdx.x;
    int r0 = blockIdx.x * 32;
    // rmsnorm: 8 threads per row
    {
        int rr = tid >> 3, p = tid & 7;
        const float* hr = g_h + (r0 + rr) * DIM + p * 8;
        float hv[8], ss = 0.f;
        #pragma unroll
        for (int j = 0; j < 8; j++) { hv[j] = hr[j]; ss += hv[j] * hv[j]; }
        ss += __shfl_xor_sync(0xffffffffu, ss, 1);
        ss += __shfl_xor_sync(0xffffffffu, ss, 2);
        ss += __shfl_xor_sync(0xffffffffu, ss, 4);
        float rs = rsqrtf(ss * (1.f / DIM) + EPSF);
        #pragma unroll
        for (int j = 0; j < 8; j++) ts[rr][p * 8 + j] = hv[j] * rs * n2w[p * 8 + j];
    }
    __syncthreads();
    int rg = tid >> 6;           // 0..3 -> rows rg*8..rg*8+7
    int k = (tid & 63) * 4;      // 4 cols
    float a1[8][4], a2[8][4];
    #pragma unroll
    for (int rr = 0; rr < 8; rr++)
        #pragma unroll
        for (int c = 0; c < 4; c++) { a1[rr][c] = 0.f; a2[rr][c] = 0.f; }
    #pragma unroll 4
    for (int d = 0; d < DIM; d++) {
        float4 w1v = *(const float4*)(g_w1t + d * HID + k);
        float4 w2v = *(const float4*)(g_w2t + d * HID + k);
        #pragma unroll
        for (int rr = 0; rr < 8; rr++) {
            float tv = ts[rg * 8 + rr][d];
            a1[rr][0] += tv * w1v.x; a1[rr][1] += tv * w1v.y;
            a1[rr][2] += tv * w1v.z; a1[rr][3] += tv * w1v.w;
            a2[rr][0] += tv * w2v.x; a2[rr][1] += tv * w2v.y;
            a2[rr][2] += tv * w2v.z; a2[rr][3] += tv * w2v.w;
        }
    }
    float4 bb1 = *(const float4*)(b1p + k);
    float4 bb2 = *(const float4*)(b2p + k);
    #pragma unroll
    for (int rr = 0; rr < 8; rr++) {
        int row = r0 + rg * 8 + rr;
        float u1x = a1[rr][0] + bb1.x, u1y = a1[rr][1] + bb1.y;
        float u1z = a1[rr][2] + bb1.z, u1w = a1[rr][3] + bb1.w;
        float4 o;
        o.x = (a2[rr][0] + bb2.x) * u1x * (1.f / (1.f + __expf(-u1x)));
        o.y = (a2[rr][1] + bb2.y) * u1y * (1.f / (1.f + __expf(-u1y)));
        o.z = (a2[rr][2] + bb2.z) * u1z * (1.f / (1.f + __expf(-u1z)));
        o.w = (a2[rr][3] + bb2.w) * u1w * (1.f / (1.f + __expf(-u1w)));
        *(float4*)(g_hid + row * HID + k) = o;
    }
}

// ---------------- K5: down-proj + residual ----------------
// 32 rows per block; thread tile 4 rows x 2 cols
__global__ void k_mlp2(const float* __restrict__ b3p, float* __restrict__ y) {
    __shared__ float hs[32][HID];  // 32KB
    int tid = threadIdx.x;
    int r0 = blockIdx.x * 32;
    for (int i = tid; i < 32 * HID; i += 256) hs[i >> 8][i & 255] = g_hid[r0 * HID + i];
    __syncthreads();
    int rg = tid >> 5;        // 0..7 -> rows rg*4..rg*4+3
    int c = (tid & 31) * 2;   // 2 cols
    float a[4][2];
    #pragma unroll
    for (int rr = 0; rr < 4; rr++) { a[rr][0] = 0.f; a[rr][1] = 0.f; }
    #pragma unroll 8
    for (int kk = 0; kk < HID; kk++) {
        float2 wv = *(const float2*)(g_w3t + kk * DIM + c);
        #pragma unroll
        for (int rr = 0; rr < 4; rr++) {
            float tv = hs[rg * 4 + rr][kk];
            a[rr][0] += tv * wv.x;
            a[rr][1] += tv * wv.y;
        }
    }
    float2 bv = *(const float2*)(b3p + c);
    #pragma unroll
    for (int rr = 0; rr < 4; rr++) {
        int row = r0 + rg * 4 + rr;
        float2 hres = *(const float2*)(g_h + row * DIM + c);
        float2 o;
        o.x = hres.x + a[rr][0] + bv.x;
        o.y = hres.y + a[rr][1] + bv.y;
        *(float2*)(y + row * DIM + c) = o;
    }
}

// ---------------- launch ----------------
extern "C" void kernel_launch(void* const* d_in, const int* in_sizes, int n_in,
                              void* d_out, int out_size) {
    const float* x    = (const float*)d_in[0];
    const float* pos  = (const float*)d_in[1];
    const float* n1w  = (const float*)d_in[2];
    const float* n2w  = (const float*)d_in[3];
    const float* w1w  = (const float*)d_in[4];
    const float* w1b  = (const float*)d_in[5];
    const float* w2w  = (const float*)d_in[6];
    const float* w2b  = (const float*)d_in[7];
    const float* w3w  = (const float*)d_in[8];
    const float* w3b  = (const float*)d_in[9];
    float* y = (float*)d_out;

    k_transpose<<<64, 256>>>(w1w, w2w, w3w);
    k_ball<<<NBALL, 256>>>(x, pos, n1w);
    k_route<<<(NPTS * NH) / 256, 256>>>();
    k_attn<<<NPTS / 4, 128>>>(x);
    k_mlp1<<<NPTS / 32, 256>>>(n2w, w1b, w2b);
    k_mlp2<<<NPTS / 32, 256>>>(w3b, y);
}

// round 2
// speedup vs baseline: 1.5972x; 1.5972x over previous
#include <cuda_runtime.h>
#include <math.h>

#define NPTS 8192
#define MB   64
#define NBALL 128
#define DIM  64
#define NH   8
#define EHD  8
#define HID  256
#define EPSF 1.1920929e-07f

// ---------------- scratch (device globals; no allocation) ----------------
__device__ float g_xat[NH * NPTS * EHD];   // head-major rmsnorm(x)+rel
__device__ float g_keyst[NH * NBALL * EHD];// head-major ball key means
__device__ int   g_idx[NH * NPTS * 2];     // top-2 ball indices, [h][n][2]
__device__ float g_h[NPTS * DIM];          // x + attn out (residual stream)
__device__ float g_hid[NPTS * HID];        // swiglu hidden
__device__ float g_w1t[DIM * HID];         // w1 transposed [d][k]
__device__ float g_w2t[DIM * HID];         // w2 transposed [d][k]
__device__ float g_w3t[HID * DIM];         // w3 transposed [k][d]

// ---------------- K0: weight transposes ----------------
__global__ void k_transpose(const float* __restrict__ w1,
                            const float* __restrict__ w2,
                            const float* __restrict__ w3) {
    int i = blockIdx.x * 256 + threadIdx.x;   // 0..16383
    if (i < DIM * HID) {
        int k = i >> 6, d = i & 63;
        g_w1t[d * HID + k] = w1[i];
        g_w2t[d * HID + k] = w2[i];
        int d3 = i >> 8, k3 = i & 255;
        g_w3t[k3 * DIM + d3] = w3[i];
    }
}

// ---------------- K1: per-ball prep ----------------
// xat = head-major( rmsnorm(x)*w + (pos - ball_mean(pos)) ); keyst = ball means
__global__ void k_ball(const float* __restrict__ x,
                       const float* __restrict__ pos,
                       const float* __restrict__ n1w) {
    __shared__ float xs[MB][DIM + 1];
    __shared__ float ps[MB][DIM + 1];
    __shared__ float pm[DIM];
    __shared__ float wsm[DIM];
    int b = blockIdx.x, tid = threadIdx.x;
    const float* xb = x + b * (MB * DIM);
    const float* pb = pos + b * (MB * DIM);
    for (int i = tid; i < MB * DIM; i += 256) {
        int r = i >> 6, d = i & 63;
        xs[r][d] = xb[i];
        ps[r][d] = pb[i];
    }
    if (tid < DIM) wsm[tid] = n1w[tid];
    __syncthreads();
    if (tid < DIM) {
        float s = 0.f;
        #pragma unroll
        for (int r = 0; r < MB; r++) s += ps[r][tid];
        pm[tid] = s * (1.f / MB);
    }
    __syncthreads();
    // 4 threads per row, 16 dims each (= 2 heads)
    int r = tid >> 2, part = tid & 3, d0 = part * 16;
    float ss = 0.f;
    #pragma unroll
    for (int j = 0; j < 16; j++) { float v = xs[r][d0 + j]; ss += v * v; }
    ss += __shfl_xor_sync(0xffffffffu, ss, 1);
    ss += __shfl_xor_sync(0xffffffffu, ss, 2);
    float rs = rsqrtf(ss * (1.f / DIM) + EPSF);
    float vals[16];
    #pragma unroll
    for (int j = 0; j < 16; j++) {
        int d = d0 + j;
        vals[j] = xs[r][d] * rs * wsm[d] + ps[r][d] - pm[d];
    }
    #pragma unroll
    for (int j = 0; j < 16; j++) xs[r][d0 + j] = vals[j];
    // head-major store: heads part*2 and part*2+1
    {
        int n = b * MB + r;
        float* o0 = g_xat + (part * 2) * (NPTS * EHD) + n * EHD;
        float* o1 = o0 + NPTS * EHD;
        ((float4*)o0)[0] = make_float4(vals[0], vals[1], vals[2], vals[3]);
        ((float4*)o0)[1] = make_float4(vals[4], vals[5], vals[6], vals[7]);
        ((float4*)o1)[0] = make_float4(vals[8], vals[9], vals[10], vals[11]);
        ((float4*)o1)[1] = make_float4(vals[12], vals[13], vals[14], vals[15]);
    }
    __syncthreads();
    if (tid < DIM) {
        float s = 0.f;
        #pragma unroll
        for (int r2 = 0; r2 < MB; r2++) s += xs[r2][tid];
        g_keyst[(tid >> 3) * (NBALL * EHD) + b * EHD + (tid & 7)] = s * (1.f / MB);
    }
}

// ---------------- K2: routing (top-2 balls per (n,h)) ----------------
// g = h*NPTS + n  -> all lanes in a warp share h: broadcast smem key reads
__global__ void k_route() {
    __shared__ float4 ks[NBALL * 2];   // this head's keys: 128 balls x 8 floats
    int g = blockIdx.x * 256 + threadIdx.x;
    int h = g >> 13;                   // NPTS = 8192 per head
    int n = g & (NPTS - 1);
    const float4* kg = (const float4*)(g_keyst + h * (NBALL * EHD));
    for (int i = threadIdx.x; i < NBALL * 2; i += 256) ks[i] = kg[i];
    __syncthreads();
    const float4* qp = (const float4*)(g_xat + h * (NPTS * EHD) + n * EHD);
    float4 qa = qp[0], qb = qp[1];
    float v0 = -3.4e38f, v1 = -3.4e38f;
    int i0 = 0, i1 = 0;
    #pragma unroll 4
    for (int b = 0; b < NBALL; b++) {
        float4 kA = ks[b * 2], kB = ks[b * 2 + 1];
        float s = qa.x * kA.x + qa.y * kA.y + qa.z * kA.z + qa.w * kA.w
                + qb.x * kB.x + qb.y * kB.y + qb.z * kB.z + qb.w * kB.w;
        if (s > v0) { v1 = v0; i1 = i0; v0 = s; i0 = b; }
        else if (s > v1) { v1 = s; i1 = b; }
    }
    g_idx[g * 2] = i0;
    g_idx[g * 2 + 1] = i1;
}

// ---------------- K3: attention (one warp per (n,h)) ----------------
__global__ void k_attn(const float* __restrict__ x) {
    int n = blockIdx.x;
    int h = threadIdx.x >> 5, lane = threadIdx.x & 31;
    const float* hb = g_xat + h * (NPTS * EHD);
    const float4* qp = (const float4*)(hb + n * EHD);
    float4 qa = qp[0], qb = qp[1];      // broadcast load
    int base = (h * NPTS + n) * 2;
    int b0 = g_idx[base], b1 = g_idx[base + 1];
    const float4* kp0 = (const float4*)(hb + b0 * (MB * EHD));
    const float4* kp1 = (const float4*)(hb + b1 * (MB * EHD));
    const float scale = 0.35355339059327373f;  // 1/sqrt(8)
    float4 kA[4], kB[4];
    float sc[4];
    #pragma unroll
    for (int ji = 0; ji < 4; ji++) {
        const float4* src = (ji < 2) ? kp0 : kp1;
        int row = lane + (ji & 1) * 32;
        kA[ji] = src[row * 2];
        kB[ji] = src[row * 2 + 1];
        sc[ji] = (qa.x * kA[ji].x + qa.y * kA[ji].y + qa.z * kA[ji].z + qa.w * kA[ji].w
                + qb.x * kB[ji].x + qb.y * kB[ji].y + qb.z * kB[ji].z + qb.w * kB[ji].w) * scale;
    }
    float m = fmaxf(fmaxf(sc[0], sc[1]), fmaxf(sc[2], sc[3]));
    #pragma unroll
    for (int o = 16; o >= 1; o >>= 1) m = fmaxf(m, __shfl_xor_sync(0xffffffffu, m, o));
    float p[4], sum = 0.f;
    #pragma unroll
    for (int ji = 0; ji < 4; ji++) { p[ji] = __expf(sc[ji] - m); sum += p[ji]; }
    #pragma unroll
    for (int o = 16; o >= 1; o >>= 1) sum += __shfl_xor_sync(0xffffffffu, sum, o);
    float inv = 1.f / sum;
    float acc[EHD];
    #pragma unroll
    for (int e = 0; e < EHD; e++) acc[e] = 0.f;
    #pragma unroll
    for (int ji = 0; ji < 4; ji++) {
        acc[0] += p[ji] * kA[ji].x; acc[1] += p[ji] * kA[ji].y;
        acc[2] += p[ji] * kA[ji].z; acc[3] += p[ji] * kA[ji].w;
        acc[4] += p[ji] * kB[ji].x; acc[5] += p[ji] * kB[ji].y;
        acc[6] += p[ji] * kB[ji].z; acc[7] += p[ji] * kB[ji].w;
    }
    float outv = 0.f;
    #pragma unroll
    for (int e = 0; e < EHD; e++) {
        float v = acc[e];
        #pragma unroll
        for (int o = 16; o >= 1; o >>= 1) v += __shfl_xor_sync(0xffffffffu, v, o);
        if (lane == e) outv = v;
    }
    if (lane < EHD) {
        int o = n * DIM + h * EHD + lane;
        g_h[o] = x[o] + outv * inv;
    }
}

// ---------------- K4: rmsnorm + dual GEMM + SwiGLU ----------------
__global__ void k_mlp1(const float* __restrict__ n2w,
                       const float* __restrict__ b1p,
                       const float* __restrict__ b2p) {
    __shared__ float ts[32][DIM + 1];
    int tid = threadIdx.x;
    int r0 = blockIdx.x * 32;
    {
        int rr = tid >> 3, p = tid & 7;
        const float* hr = g_h + (r0 + rr) * DIM + p * 8;
        float hv[8], ss = 0.f;
        #pragma unroll
        for (int j = 0; j < 8; j++) { hv[j] = hr[j]; ss += hv[j] * hv[j]; }
        ss += __shfl_xor_sync(0xffffffffu, ss, 1);
        ss += __shfl_xor_sync(0xffffffffu, ss, 2);
        ss += __shfl_xor_sync(0xffffffffu, ss, 4);
        float rs = rsqrtf(ss * (1.f / DIM) + EPSF);
        #pragma unroll
        for (int j = 0; j < 8; j++) ts[rr][p * 8 + j] = hv[j] * rs * n2w[p * 8 + j];
    }
    __syncthreads();
    int rg = tid >> 6;
    int k = (tid & 63) * 4;
    float a1[8][4], a2[8][4];
    #pragma unroll
    for (int rr = 0; rr < 8; rr++)
        #pragma unroll
        for (int c = 0; c < 4; c++) { a1[rr][c] = 0.f; a2[rr][c] = 0.f; }
    #pragma unroll 4
    for (int d = 0; d < DIM; d++) {
        float4 w1v = *(const float4*)(g_w1t + d * HID + k);
        float4 w2v = *(const float4*)(g_w2t + d * HID + k);
        #pragma unroll
        for (int rr = 0; rr < 8; rr++) {
            float tv = ts[rg * 8 + rr][d];
            a1[rr][0] += tv * w1v.x; a1[rr][1] += tv * w1v.y;
            a1[rr][2] += tv * w1v.z; a1[rr][3] += tv * w1v.w;
            a2[rr][0] += tv * w2v.x; a2[rr][1] += tv * w2v.y;
            a2[rr][2] += tv * w2v.z; a2[rr][3] += tv * w2v.w;
        }
    }
    float4 bb1 = *(const float4*)(b1p + k);
    float4 bb2 = *(const float4*)(b2p + k);
    #pragma unroll
    for (int rr = 0; rr < 8; rr++) {
        int row = r0 + rg * 8 + rr;
        float u1x = a1[rr][0] + bb1.x, u1y = a1[rr][1] + bb1.y;
        float u1z = a1[rr][2] + bb1.z, u1w = a1[rr][3] + bb1.w;
        float4 o;
        o.x = (a2[rr][0] + bb2.x) * u1x * (1.f / (1.f + __expf(-u1x)));
        o.y = (a2[rr][1] + bb2.y) * u1y * (1.f / (1.f + __expf(-u1y)));
        o.z = (a2[rr][2] + bb2.z) * u1z * (1.f / (1.f + __expf(-u1z)));
        o.w = (a2[rr][3] + bb2.w) * u1w * (1.f / (1.f + __expf(-u1w)));
        *(float4*)(g_hid + row * HID + k) = o;
    }
}

// ---------------- K5: down-proj + residual ----------------
__global__ void k_mlp2(const float* __restrict__ b3p, float* __restrict__ y) {
    __shared__ float hs[32][HID];
    int tid = threadIdx.x;
    int r0 = blockIdx.x * 32;
    for (int i = tid; i < 32 * HID; i += 256) hs[i >> 8][i & 255] = g_hid[r0 * HID + i];
    __syncthreads();
    int rg = tid >> 5;
    int c = (tid & 31) * 2;
    float a[4][2];
    #pragma unroll
    for (int rr = 0; rr < 4; rr++) { a[rr][0] = 0.f; a[rr][1] = 0.f; }
    #pragma unroll 8
    for (int kk = 0; kk < HID; kk++) {
        float2 wv = *(const float2*)(g_w3t + kk * DIM + c);
        #pragma unroll
        for (int rr = 0; rr < 4; rr++) {
            float tv = hs[rg * 4 + rr][kk];
            a[rr][0] += tv * wv.x;
            a[rr][1] += tv * wv.y;
        }
    }
    float2 bv = *(const float2*)(b3p + c);
    #pragma unroll
    for (int rr = 0; rr < 4; rr++) {
        int row = r0 + rg * 4 + rr;
        float2 hres = *(const float2*)(g_h + row * DIM + c);
        float2 o;
        o.x = hres.x + a[rr][0] + bv.x;
        o.y = hres.y + a[rr][1] + bv.y;
        *(float2*)(y + row * DIM + c) = o;
    }
}

// ---------------- launch ----------------
extern "C" void kernel_launch(void* const* d_in, const int* in_sizes, int n_in,
                              void* d_out, int out_size) {
    const float* x    = (const float*)d_in[0];
    const float* pos  = (const float*)d_in[1];
    const float* n1w  = (const float*)d_in[2];
    const float* n2w  = (const float*)d_in[3];
    const float* w1w  = (const float*)d_in[4];
    const float* w1b  = (const float*)d_in[5];
    const float* w2w  = (const float*)d_in[6];
    const float* w2b  = (const float*)d_in[7];
    const float* w3w  = (const float*)d_in[8];
    const float* w3b  = (const float*)d_in[9];
    float* y = (float*)d_out;

    k_transpose<<<64, 256>>>(w1w, w2w, w3w);
    k_ball<<<NBALL, 256>>>(x, pos, n1w);
    k_route<<<(NPTS * NH) / 256, 256>>>();
    k_attn<<<NPTS, 256>>>(x);
    k_mlp1<<<NPTS / 32, 256>>>(n2w, w1b, w2b);
    k_mlp2<<<NPTS / 32, 256>>>(w3b, y);
}

// round 3
// speedup vs baseline: 1.6272x; 1.0188x over previous
#include <cuda_runtime.h>
#include <math.h>

#define NPTS 8192
#define MB   64
#define NBALL 128
#define DIM  64
#define NH   8
#define EHD  8
#define HID  256
#define EPSF 1.1920929e-07f

// ---------------- scratch (device globals; no allocation) ----------------
__device__ float g_xat[NH * NPTS * EHD];   // head-major rmsnorm(x)+rel
__device__ float g_keyst[NH * NBALL * EHD];// head-major ball key means
__device__ int   g_idx[NH * NPTS * 2];     // top-2 ball indices, [h][n][2]
__device__ float g_h[NPTS * DIM];          // x + attn out (residual stream)
__device__ float g_hid[NPTS * HID];        // swiglu hidden
__device__ float g_w1t[DIM * HID];         // w1 transposed [d][k]
__device__ float g_w2t[DIM * HID];         // w2 transposed [d][k]
__device__ float g_w3t[HID * DIM];         // w3 transposed [k][d]

// ---------------- K1: per-ball prep + weight transpose (fused) ----------------
__global__ void k_prep(const float* __restrict__ x,
                       const float* __restrict__ pos,
                       const float* __restrict__ n1w,
                       const float* __restrict__ w1,
                       const float* __restrict__ w2,
                       const float* __restrict__ w3) {
    int blk = blockIdx.x, tid = threadIdx.x;
    if (blk >= NBALL) {
        // weight transpose blocks
        int i = (blk - NBALL) * 256 + tid;   // 0..16383
        int k = i >> 6, d = i & 63;
        g_w1t[d * HID + k] = w1[i];
        g_w2t[d * HID + k] = w2[i];
        int d3 = i >> 8, k3 = i & 255;
        g_w3t[k3 * DIM + d3] = w3[i];
        return;
    }
    __shared__ float xs[MB][DIM + 1];
    __shared__ float ps[MB][DIM + 1];
    __shared__ float pm[DIM];
    __shared__ float wsm[DIM];
    int b = blk;
    const float* xb = x + b * (MB * DIM);
    const float* pb = pos + b * (MB * DIM);
    for (int i = tid; i < MB * DIM; i += 256) {
        int r = i >> 6, d = i & 63;
        xs[r][d] = xb[i];
        ps[r][d] = pb[i];
    }
    if (tid < DIM) wsm[tid] = n1w[tid];
    __syncthreads();
    if (tid < DIM) {
        float s = 0.f;
        #pragma unroll
        for (int r = 0; r < MB; r++) s += ps[r][tid];
        pm[tid] = s * (1.f / MB);
    }
    __syncthreads();
    // 4 threads per row, 16 dims each (= 2 heads)
    int r = tid >> 2, part = tid & 3, d0 = part * 16;
    float ss = 0.f;
    #pragma unroll
    for (int j = 0; j < 16; j++) { float v = xs[r][d0 + j]; ss += v * v; }
    ss += __shfl_xor_sync(0xffffffffu, ss, 1);
    ss += __shfl_xor_sync(0xffffffffu, ss, 2);
    float rs = rsqrtf(ss * (1.f / DIM) + EPSF);
    float vals[16];
    #pragma unroll
    for (int j = 0; j < 16; j++) {
        int d = d0 + j;
        vals[j] = xs[r][d] * rs * wsm[d] + ps[r][d] - pm[d];
    }
    #pragma unroll
    for (int j = 0; j < 16; j++) xs[r][d0 + j] = vals[j];
    {
        int n = b * MB + r;
        float* o0 = g_xat + (part * 2) * (NPTS * EHD) + n * EHD;
        float* o1 = o0 + NPTS * EHD;
        ((float4*)o0)[0] = make_float4(vals[0], vals[1], vals[2], vals[3]);
        ((float4*)o0)[1] = make_float4(vals[4], vals[5], vals[6], vals[7]);
        ((float4*)o1)[0] = make_float4(vals[8], vals[9], vals[10], vals[11]);
        ((float4*)o1)[1] = make_float4(vals[12], vals[13], vals[14], vals[15]);
    }
    __syncthreads();
    if (tid < DIM) {
        float s = 0.f;
        #pragma unroll
        for (int r2 = 0; r2 < MB; r2++) s += xs[r2][tid];
        g_keyst[(tid >> 3) * (NBALL * EHD) + b * EHD + (tid & 7)] = s * (1.f / MB);
    }
}

// ---------------- K2: routing (top-2 balls per (n,h)) ----------------
__global__ void k_route() {
    __shared__ float4 ks[NBALL * 2];   // this head's keys
    int g = blockIdx.x * 256 + threadIdx.x;
    int h = g >> 13;                   // NPTS = 8192 per head
    int n = g & (NPTS - 1);
    const float4* kg = (const float4*)(g_keyst + h * (NBALL * EHD));
    for (int i = threadIdx.x; i < NBALL * 2; i += 256) ks[i] = kg[i];
    __syncthreads();
    const float4* qp = (const float4*)(g_xat + h * (NPTS * EHD) + n * EHD);
    float4 qa = qp[0], qb = qp[1];
    float v0 = -3.4e38f, v1 = -3.4e38f;
    int i0 = 0, i1 = 0;
    #pragma unroll 4
    for (int b = 0; b < NBALL; b++) {
        float4 kA = ks[b * 2], kB = ks[b * 2 + 1];
        float s = qa.x * kA.x + qa.y * kA.y + qa.z * kA.z + qa.w * kA.w
                + qb.x * kB.x + qb.y * kB.y + qb.z * kB.z + qb.w * kB.w;
        if (s > v0) { v1 = v0; i1 = i0; v0 = s; i0 = b; }
        else if (s > v1) { v1 = s; i1 = b; }
    }
    g_idx[g * 2] = i0;
    g_idx[g * 2 + 1] = i1;
}

// ---------------- K3: attention (one warp per (n,h), coalesced lane-pair) ----
// Each lane loads contiguous float4s; lane owns half-rows (even lane: elems 0-3,
// odd lane: elems 4-7). Pair-shuffle builds full scores; parity reduction builds
// the two output halves.
__global__ void k_attn(const float* __restrict__ x) {
    int n = blockIdx.x;
    int h = threadIdx.x >> 5, lane = threadIdx.x & 31;
    const float* hb = g_xat + h * (NPTS * EHD);
    const float4* qp = (const float4*)(hb + n * EHD);
    float4 qa = qp[0], qb = qp[1];
    float4 qh = (lane & 1) ? qb : qa;
    int base = (h * NPTS + n) * 2;
    int b0 = g_idx[base], b1 = g_idx[base + 1];
    const float4* p0 = (const float4*)(hb + b0 * (MB * EHD));
    const float4* p1 = (const float4*)(hb + b1 * (MB * EHD));
    const float scale = 0.35355339059327373f;  // 1/sqrt(8)

    float4 v[8];
    #pragma unroll
    for (int c = 0; c < 4; c++) v[c] = p0[c * 32 + lane];
    #pragma unroll
    for (int c = 0; c < 4; c++) v[4 + c] = p1[c * 32 + lane];

    float s[8];
    #pragma unroll
    for (int i = 0; i < 8; i++) {
        float part = qh.x * v[i].x + qh.y * v[i].y + qh.z * v[i].z + qh.w * v[i].w;
        s[i] = (part + __shfl_xor_sync(0xffffffffu, part, 1)) * scale;
    }
    float m = s[0];
    #pragma unroll
    for (int i = 1; i < 8; i++) m = fmaxf(m, s[i]);
    #pragma unroll
    for (int o = 16; o >= 1; o >>= 1) m = fmaxf(m, __shfl_xor_sync(0xffffffffu, m, o));
    float p[8], lsum = 0.f;
    #pragma unroll
    for (int i = 0; i < 8; i++) { p[i] = __expf(s[i] - m); lsum += p[i]; }
    #pragma unroll
    for (int o = 16; o >= 1; o >>= 1) lsum += __shfl_xor_sync(0xffffffffu, lsum, o);
    float inv = 2.f / lsum;   // every row counted twice across the warp

    float4 acc = make_float4(0.f, 0.f, 0.f, 0.f);
    #pragma unroll
    for (int i = 0; i < 8; i++) {
        acc.x += p[i] * v[i].x; acc.y += p[i] * v[i].y;
        acc.z += p[i] * v[i].z; acc.w += p[i] * v[i].w;
    }
    #pragma unroll
    for (int o = 2; o <= 16; o <<= 1) {
        acc.x += __shfl_xor_sync(0xffffffffu, acc.x, o);
        acc.y += __shfl_xor_sync(0xffffffffu, acc.y, o);
        acc.z += __shfl_xor_sync(0xffffffffu, acc.z, o);
        acc.w += __shfl_xor_sync(0xffffffffu, acc.w, o);
    }
    if (lane < 2) {
        int off = n * DIM + h * EHD + lane * 4;
        float4 xr = *(const float4*)(x + off);
        float4 o;
        o.x = xr.x + acc.x * inv;
        o.y = xr.y + acc.y * inv;
        o.z = xr.z + acc.z * inv;
        o.w = xr.w + acc.w * inv;
        *(float4*)(g_h + off) = o;
    }
}

// ---------------- K4: rmsnorm + dual GEMM + SwiGLU ----------------
__global__ void k_mlp1(const float* __restrict__ n2w,
                       const float* __restrict__ b1p,
                       const float* __restrict__ b2p) {
    __shared__ float ts[32][DIM + 1];
    int tid = threadIdx.x;
    int r0 = blockIdx.x * 32;
    {
        int rr = tid >> 3, p = tid & 7;
        const float* hr = g_h + (r0 + rr) * DIM + p * 8;
        float hv[8], ss = 0.f;
        #pragma unroll
        for (int j = 0; j < 8; j++) { hv[j] = hr[j]; ss += hv[j] * hv[j]; }
        ss += __shfl_xor_sync(0xffffffffu, ss, 1);
        ss += __shfl_xor_sync(0xffffffffu, ss, 2);
        ss += __shfl_xor_sync(0xffffffffu, ss, 4);
        float rs = rsqrtf(ss * (1.f / DIM) + EPSF);
        #pragma unroll
        for (int j = 0; j < 8; j++) ts[rr][p * 8 + j] = hv[j] * rs * n2w[p * 8 + j];
    }
    __syncthreads();
    int rg = tid >> 6;
    int k = (tid & 63) * 4;
    float a1[8][4], a2[8][4];
    #pragma unroll
    for (int rr = 0; rr < 8; rr++)
        #pragma unroll
        for (int c = 0; c < 4; c++) { a1[rr][c] = 0.f; a2[rr][c] = 0.f; }
    #pragma unroll 8
    for (int d = 0; d < DIM; d++) {
        float4 w1v = *(const float4*)(g_w1t + d * HID + k);
        float4 w2v = *(const float4*)(g_w2t + d * HID + k);
        #pragma unroll
        for (int rr = 0; rr < 8; rr++) {
            float tv = ts[rg * 8 + rr][d];
            a1[rr][0] += tv * w1v.x; a1[rr][1] += tv * w1v.y;
            a1[rr][2] += tv * w1v.z; a1[rr][3] += tv * w1v.w;
            a2[rr][0] += tv * w2v.x; a2[rr][1] += tv * w2v.y;
            a2[rr][2] += tv * w2v.z; a2[rr][3] += tv * w2v.w;
        }
    }
    float4 bb1 = *(const float4*)(b1p + k);
    float4 bb2 = *(const float4*)(b2p + k);
    #pragma unroll
    for (int rr = 0; rr < 8; rr++) {
        int row = r0 + rg * 8 + rr;
        float u1x = a1[rr][0] + bb1.x, u1y = a1[rr][1] + bb1.y;
        float u1z = a1[rr][2] + bb1.z, u1w = a1[rr][3] + bb1.w;
        float4 o;
        o.x = (a2[rr][0] + bb2.x) * u1x * (1.f / (1.f + __expf(-u1x)));
        o.y = (a2[rr][1] + bb2.y) * u1y * (1.f / (1.f + __expf(-u1y)));
        o.z = (a2[rr][2] + bb2.z) * u1z * (1.f / (1.f + __expf(-u1z)));
        o.w = (a2[rr][3] + bb2.w) * u1w * (1.f / (1.f + __expf(-u1w)));
        *(float4*)(g_hid + row * HID + k) = o;
    }
}

// ---------------- K5: down-proj + residual (4x4 thread tiles) ----------------
__global__ void k_mlp2(const float* __restrict__ b3p, float* __restrict__ y) {
    __shared__ float hs[32][HID];   // 32 KB
    int tid = threadIdx.x;          // 128 threads
    int r0 = blockIdx.x * 32;
    {
        const float4* src = (const float4*)(g_hid + r0 * HID);
        float4* dst = (float4*)&hs[0][0];
        for (int i = tid; i < 32 * HID / 4; i += 128) dst[i] = src[i];
    }
    __syncthreads();
    int rg = tid >> 4;        // 0..7 -> rows rg*4..rg*4+3
    int c = (tid & 15) * 4;   // 4 cols
    float a[4][4];
    #pragma unroll
    for (int rr = 0; rr < 4; rr++)
        #pragma unroll
        for (int cc = 0; cc < 4; cc++) a[rr][cc] = 0.f;
    #pragma unroll 8
    for (int kk = 0; kk < HID; kk++) {
        float4 wv = *(const float4*)(g_w3t + kk * DIM + c);
        #pragma unroll
        for (int rr = 0; rr < 4; rr++) {
            float tv = hs[rg * 4 + rr][kk];
            a[rr][0] += tv * wv.x; a[rr][1] += tv * wv.y;
            a[rr][2] += tv * wv.z; a[rr][3] += tv * wv.w;
        }
    }
    float4 bv = *(const float4*)(b3p + c);
    #pragma unroll
    for (int rr = 0; rr < 4; rr++) {
        int row = r0 + rg * 4 + rr;
        float4 hres = *(const float4*)(g_h + row * DIM + c);
        float4 o;
        o.x = hres.x + a[rr][0] + bv.x;
        o.y = hres.y + a[rr][1] + bv.y;
        o.z = hres.z + a[rr][2] + bv.z;
        o.w = hres.w + a[rr][3] + bv.w;
        *(float4*)(y + row * DIM + c) = o;
    }
}

// ---------------- launch ----------------
extern "C" void kernel_launch(void* const* d_in, const int* in_sizes, int n_in,
                              void* d_out, int out_size) {
    const float* x    = (const float*)d_in[0];
    const float* pos  = (const float*)d_in[1];
    const float* n1w  = (const float*)d_in[2];
    const float* n2w  = (const float*)d_in[3];
    const float* w1w  = (const float*)d_in[4];
    const float* w1b  = (const float*)d_in[5];
    const float* w2w  = (const float*)d_in[6];
    const float* w2b  = (const float*)d_in[7];
    const float* w3w  = (const float*)d_in[8];
    const float* w3b  = (const float*)d_in[9];
    float* y = (float*)d_out;

    k_prep<<<NBALL + 64, 256>>>(x, pos, n1w, w1w, w2w, w3w);
    k_route<<<(NPTS * NH) / 256, 256>>>();
    k_attn<<<NPTS, 256>>>(x);
    k_mlp1<<<NPTS / 32, 256>>>(n2w, w1b, w2b);
    k_mlp2<<<NPTS / 32, 128>>>(w3b, y);
}